// round 12
// baseline (speedup 1.0000x reference)
#include <cuda_runtime.h>
#include <cuda_fp16.h>
#include <cstdint>

#define N_NODES   20000
#define M_PAD     20096      // 314 * 64
#define M_LO      10048      // 157 * 64 — split point for scatter/GEMM overlap
#define IN_DIM    256
#define OUT_DIM   256
#define FOLD_DIM  128        // 32 q-groups * 4 bases
#define K_DIM     1024       // 8 relations * 128

// Scratch (static device globals — no allocation allowed)
__device__ __half g_hf[N_NODES * FOLD_DIM];        // folded h  [N, 128] fp16
__device__ __half g_U [(size_t)M_PAD * K_DIM];     // aggregated [M_PAD, 1024] fp16
__device__ __half g_Bt[(size_t)OUT_DIM * K_DIM];   // basis^T, K-major, fp16

// ---------------------------------------------------------------------------
// Kernel 1: fold h with w_comp.  hf[n, q*4+b] = sum_p h[n, q*8+p] * w_comp[p,b]
// ---------------------------------------------------------------------------
__global__ void fold_kernel(const float* __restrict__ h,
                            const float* __restrict__ w_comp, int N) {
    __shared__ float wc[32];
    if (threadIdx.x < 32) wc[threadIdx.x] = w_comp[threadIdx.x];
    __syncthreads();

    int idx = blockIdx.x * blockDim.x + threadIdx.x;
    if (idx >= N * 32) return;
    int n = idx >> 5;
    int q = idx & 31;

    const float4* hp = reinterpret_cast<const float4*>(h + (size_t)n * IN_DIM + q * 8);
    float4 h0 = hp[0];
    float4 h1 = hp[1];
    float hv[8] = {h0.x, h0.y, h0.z, h0.w, h1.x, h1.y, h1.z, h1.w};

    float o[4];
    #pragma unroll
    for (int b = 0; b < 4; b++) {
        float s = 0.f;
        #pragma unroll
        for (int p = 0; p < 8; p++) s += hv[p] * wc[p * 4 + b];
        o[b] = s;
    }
    __half2 p0 = __floats2half2_rn(o[0], o[1]);
    __half2 p1 = __floats2half2_rn(o[2], o[3]);
    __half2* d = reinterpret_cast<__half2*>(g_hf + (size_t)n * FOLD_DIM + q * 4);
    d[0] = p0;
    d[1] = p1;
}

// ---------------------------------------------------------------------------
// Kernel 2: transpose basis [1024,256] -> g_Bt [256,1024] (K-major) as fp16.
// ---------------------------------------------------------------------------
__global__ void transpose_kernel(const float* __restrict__ basis) {
    __shared__ float t[32][33];
    int bx = blockIdx.x;
    int by = blockIdx.y;
    int x = threadIdx.x;
    int y = threadIdx.y;
    #pragma unroll
    for (int i = 0; i < 4; i++)
        t[y + i * 8][x] = basis[(size_t)(bx * 32 + y + i * 8) * OUT_DIM + by * 32 + x];
    __syncthreads();
    #pragma unroll
    for (int i = 0; i < 4; i++)
        g_Bt[(size_t)(by * 32 + y + i * 8) * K_DIM + bx * 32 + x] =
            __float2half_rn(t[x][y + i * 8]);
}

// ---------------------------------------------------------------------------
// Kernel 3: edge scatter, fp16, restricted to dst in [dlo, dhi).
// 16 lanes per edge, red.add.noftz.v4.f16x2
// ---------------------------------------------------------------------------
__global__ void scatter_kernel(const int* __restrict__ src,
                               const int* __restrict__ dst,
                               const int* __restrict__ etype, int E,
                               int dlo, int dhi) {
    int warp = (blockIdx.x * blockDim.x + threadIdx.x) >> 5;
    int lane = threadIdx.x & 31;
    int e = warp * 2 + (lane >> 4);
    int l = lane & 15;
    if (e >= E) return;

    int d = __ldg(dst + e);
    if (d < dlo || d >= dhi) return;
    int s = __ldg(src + e);
    int r = __ldg(etype + e);

    uint4 v = *reinterpret_cast<const uint4*>(g_hf + (size_t)s * FOLD_DIM + l * 8);
    __half* up = g_U + (size_t)d * K_DIM + r * FOLD_DIM + l * 8;
    asm volatile("red.global.add.noftz.v4.f16x2 [%0], {%1, %2, %3, %4};"
                 :: "l"(up), "r"(v.x), "r"(v.y), "r"(v.z), "r"(v.w)
                 : "memory");
}

// ---------------------------------------------------------------------------
// Kernel 4: fp16 tensor-core GEMM + bias + relu over rows [bm0, bm0+gridDim.y*64)
// CTA 64x64, 128 threads, 2x2 warp grid (warp tile 32x32), ~5 CTAs/SM.
// BK=64, 2-stage cp.async, SW128 smem, ldmatrix with PRECOMPUTED addresses
// (SWZ(row*128+kb) == row*128 + (kb ^ c_row) — carry-free, loop-invariant).
// ---------------------------------------------------------------------------
#define GBM 64
#define GBN 64
#define GBK 64
#define STAGE_BYTES (GBM * 128)                       // 8 KB per operand-stage
#define GEMM_SMEM_BYTES (2 * 2 * STAGE_BYTES)         // 32768 B

#define SWZ(o) ((o) ^ (((o) >> 3) & 0x70))

__device__ __forceinline__ uint32_t smem_u32(const void* p) {
    return (uint32_t)__cvta_generic_to_shared(p);
}

__global__ __launch_bounds__(128, 5)
void gemm_tc_kernel(const __half* __restrict__ Bt,
                    const float* __restrict__ bias,
                    float* __restrict__ out, int M, int bm0) {
    extern __shared__ char smem[];
    char* As = smem;                        // [2][64 rows][128 B] swizzled
    char* Bs = smem + 2 * STAGE_BYTES;      // [2][64 rows][128 B] swizzled

    int tid  = threadIdx.x;
    int lane = tid & 31;
    int warp = tid >> 5;
    int wm = warp & 1;                      // rows wm*32
    int wn = warp >> 1;                     // cols wn*32
    int bm = bm0 + blockIdx.y * GBM;
    int bn = blockIdx.x * GBN;

    float acc[2][4][4];                     // [mf][nf][4]
    #pragma unroll
    for (int mf = 0; mf < 2; mf++)
        #pragma unroll
        for (int nf = 0; nf < 4; nf++)
            #pragma unroll
            for (int i = 0; i < 4; i++) acc[mf][nf][i] = 0.f;

    // cp.async staging: 512 16B-segments per operand-stage; 4 per thread
    #define ISSUE_STAGE(stg, k0)                                                    \
        do {                                                                        \
            _Pragma("unroll")                                                       \
            for (int i = 0; i < 4; i++) {                                           \
                int idx = tid + i * 128;                                            \
                int row = idx >> 3;                                                 \
                int seg = idx & 7;                                                  \
                int so  = SWZ(row * 128 + seg * 16);                                \
                uint32_t da = smem_u32(As + (stg) * STAGE_BYTES + so);              \
                const __half* sa = g_U + (size_t)(bm + row) * K_DIM + (k0) + seg * 8; \
                asm volatile("cp.async.cg.shared.global [%0], [%1], 16;"            \
                             :: "r"(da), "l"(sa) : "memory");                       \
                uint32_t db = smem_u32(Bs + (stg) * STAGE_BYTES + so);              \
                const __half* sb = Bt + (size_t)(bn + row) * K_DIM + (k0) + seg * 8;  \
                asm volatile("cp.async.cg.shared.global [%0], [%1], 16;"            \
                             :: "r"(db), "l"(sb) : "memory");                       \
            }                                                                       \
            asm volatile("cp.async.commit_group;" ::: "memory");                    \
        } while (0)

    // prologue
    ISSUE_STAGE(0, 0);

    // ldmatrix lane geometry + PRECOMPUTED stage-0 addresses
    int frow = lane & 15;          // row within 16-row block
    int fkb  = (lane >> 4) * 16;   // 0 or 16 bytes

    uint32_t aaddr[2][4], baddr[2][4];
    {
        uint32_t abase = smem_u32(As);
        uint32_t bbase = smem_u32(Bs);
        #pragma unroll
        for (int mf = 0; mf < 2; mf++) {
            int row = wm * 32 + mf * 16 + frow;
            uint32_t c = ((row * 128) >> 3) & 0x70;
            #pragma unroll
            for (int ks = 0; ks < 4; ks++)
                aaddr[mf][ks] = abase + row * 128 + ((uint32_t)(ks * 32 + fkb) ^ c);
        }
        #pragma unroll
        for (int p = 0; p < 2; p++) {
            int row = wn * 32 + p * 16 + frow;
            uint32_t c = ((row * 128) >> 3) & 0x70;
            #pragma unroll
            for (int ks = 0; ks < 4; ks++)
                baddr[p][ks] = bbase + row * 128 + ((uint32_t)(ks * 32 + fkb) ^ c);
        }
    }

    const int NITER = K_DIM / GBK;   // 16
    for (int it = 0; it < NITER; ++it) {
        uint32_t coff = (it & 1) ? (uint32_t)STAGE_BYTES : 0u;

        asm volatile("cp.async.wait_group 0;" ::: "memory");
        __syncthreads();

        if (it + 1 < NITER) ISSUE_STAGE((it + 1) & 1, (it + 1) * GBK);

        #pragma unroll
        for (int ks = 0; ks < 4; ks++) {          // four k16 steps per BK=64
            uint32_t afr[2][4];
            #pragma unroll
            for (int mf = 0; mf < 2; mf++) {
                asm volatile(
                    "ldmatrix.sync.aligned.m8n8.x4.shared.b16 {%0,%1,%2,%3}, [%4];"
                    : "=r"(afr[mf][0]), "=r"(afr[mf][1]),
                      "=r"(afr[mf][2]), "=r"(afr[mf][3])
                    : "r"(aaddr[mf][ks] + coff));
            }
            uint32_t bfr[4][2];
            #pragma unroll
            for (int p = 0; p < 2; p++) {         // nf pair {2p, 2p+1}
                uint32_t r0, r1, r2, r3;
                asm volatile(
                    "ldmatrix.sync.aligned.m8n8.x4.shared.b16 {%0,%1,%2,%3}, [%4];"
                    : "=r"(r0), "=r"(r1), "=r"(r2), "=r"(r3)
                    : "r"(baddr[p][ks] + coff));
                bfr[2 * p][0] = r0; bfr[2 * p + 1][0] = r1;
                bfr[2 * p][1] = r2; bfr[2 * p + 1][1] = r3;
            }
            #pragma unroll
            for (int mf = 0; mf < 2; mf++)
                #pragma unroll
                for (int nf = 0; nf < 4; nf++)
                    asm volatile(
                        "mma.sync.aligned.m16n8k16.row.col.f32.f16.f16.f32 "
                        "{%0,%1,%2,%3}, {%4,%5,%6,%7}, {%8,%9}, {%0,%1,%2,%3};"
                        : "+f"(acc[mf][nf][0]), "+f"(acc[mf][nf][1]),
                          "+f"(acc[mf][nf][2]), "+f"(acc[mf][nf][3])
                        : "r"(afr[mf][0]), "r"(afr[mf][1]),
                          "r"(afr[mf][2]), "r"(afr[mf][3]),
                          "r"(bfr[nf][0]), "r"(bfr[nf][1]));
        }
    }

    // epilogue: + bias, relu
    #pragma unroll
    for (int mf = 0; mf < 2; mf++) {
        int row0 = bm + wm * 32 + mf * 16 + (lane >> 2);
        #pragma unroll
        for (int nf = 0; nf < 4; nf++) {
            int col = bn + wn * 32 + nf * 8 + (lane & 3) * 2;
            float b0 = __ldg(bias + col);
            float b1 = __ldg(bias + col + 1);
            if (row0 < M) {
                float2 o;
                o.x = fmaxf(acc[mf][nf][0] + b0, 0.f);
                o.y = fmaxf(acc[mf][nf][1] + b1, 0.f);
                *reinterpret_cast<float2*>(out + (size_t)row0 * OUT_DIM + col) = o;
            }
            if (row0 + 8 < M) {
                float2 o;
                o.x = fmaxf(acc[mf][nf][2] + b0, 0.f);
                o.y = fmaxf(acc[mf][nf][3] + b1, 0.f);
                *reinterpret_cast<float2*>(out + (size_t)(row0 + 8) * OUT_DIM + col) = o;
            }
        }
    }
}

// ---------------------------------------------------------------------------
extern "C" void kernel_launch(void* const* d_in, const int* in_sizes, int n_in,
                              void* d_out, int out_size) {
    const float* h      = (const float*)d_in[0];
    const float* basis  = (const float*)d_in[1];
    const float* w_comp = (const float*)d_in[2];
    const float* bias   = (const float*)d_in[3];
    const int*   src    = (const int*)d_in[4];
    const int*   dst    = (const int*)d_in[5];
    const int*   etype  = (const int*)d_in[6];
    float* out = (float*)d_out;

    int N = in_sizes[0] / IN_DIM;   // 20000
    int E = in_sizes[4];            // 320000

    static cudaStream_t s1 = nullptr, s2 = nullptr;
    static cudaEvent_t e0 = nullptr, e_m0 = nullptr, e_m1 = nullptr,
                       e_tr = nullptr, e_f = nullptr, e_s0 = nullptr,
                       e_s1 = nullptr;
    static bool init_done = false;
    if (!init_done) {
        cudaFuncSetAttribute(gemm_tc_kernel,
                             cudaFuncAttributeMaxDynamicSharedMemorySize,
                             GEMM_SMEM_BYTES);
        cudaStreamCreateWithFlags(&s1, cudaStreamNonBlocking);
        cudaStreamCreateWithFlags(&s2, cudaStreamNonBlocking);
        cudaEventCreateWithFlags(&e0,  cudaEventDisableTiming);
        cudaEventCreateWithFlags(&e_m0, cudaEventDisableTiming);
        cudaEventCreateWithFlags(&e_m1, cudaEventDisableTiming);
        cudaEventCreateWithFlags(&e_tr, cudaEventDisableTiming);
        cudaEventCreateWithFlags(&e_f,  cudaEventDisableTiming);
        cudaEventCreateWithFlags(&e_s0, cudaEventDisableTiming);
        cudaEventCreateWithFlags(&e_s1, cudaEventDisableTiming);
        init_done = true;
    }

    char* uptr = nullptr;
    cudaGetSymbolAddress((void**)&uptr, g_U);
    __half* btp = nullptr;
    cudaGetSymbolAddress((void**)&btp, g_Bt);

    const size_t lo_bytes = (size_t)M_LO * K_DIM * sizeof(__half);
    const size_t hi_bytes = (size_t)(M_PAD - M_LO) * K_DIM * sizeof(__half);

    // fork side streams
    cudaEventRecord(e0, 0);
    cudaStreamWaitEvent(s1, e0, 0);
    cudaStreamWaitEvent(s2, e0, 0);

    // s1: memset lower half, then upper half
    cudaMemsetAsync(uptr, 0, lo_bytes, s1);                                // #1
    cudaEventRecord(e_m0, s1);
    cudaMemsetAsync(uptr + lo_bytes, 0, hi_bytes, s1);                     // #2
    cudaEventRecord(e_m1, s1);

    // s2: transpose (needed only by GEMM)
    transpose_kernel<<<dim3(32, 8), dim3(32, 8), 0, s2>>>(basis);          // #3
    cudaEventRecord(e_tr, s2);

    // main: fold
    fold_kernel<<<(N * 32 + 255) / 256, 256>>>(h, w_comp, N);              // #4
    cudaEventRecord(e_f, 0);

    // main: scatter lower half (needs memset-lo + fold)
    cudaStreamWaitEvent(0, e_m0, 0);
    scatter_kernel<<<(E + 15) / 16, 256>>>(src, dst, etype, E, 0, M_LO);   // #5 (ncu)
    cudaEventRecord(e_s0, 0);

    // main: GEMM lower rows (needs Bt)
    cudaStreamWaitEvent(0, e_tr, 0);
    gemm_tc_kernel<<<dim3(OUT_DIM / GBN, M_LO / GBM), 128, GEMM_SMEM_BYTES>>>(
        btp, bias, out, N, 0);                                             // #6

    // s1: scatter upper half — starts when gemm-lo starts (after e_s0), overlaps it
    cudaStreamWaitEvent(s1, e_f, 0);
    cudaStreamWaitEvent(s1, e_s0, 0);
    scatter_kernel<<<(E + 15) / 16, 256, 0, s1>>>(src, dst, etype, E, M_LO, N); // #7
    cudaEventRecord(e_s1, s1);

    // main: GEMM upper rows (queues behind gemm-lo, fills as it drains)
    cudaStreamWaitEvent(0, e_s1, 0);
    gemm_tc_kernel<<<dim3(OUT_DIM / GBN, (M_PAD - M_LO) / GBM), 128,
                     GEMM_SMEM_BYTES>>>(btp, bias, out, N, M_LO);          // #8
}

// round 13
// speedup vs baseline: 1.3518x; 1.3518x over previous
#include <cuda_runtime.h>
#include <cuda_fp16.h>
#include <cstdint>

#define N_NODES   20000
#define M_PAD     20096      // 314 * 64
#define IN_DIM    256
#define OUT_DIM   256
#define FOLD_DIM  128        // 32 q-groups * 4 bases
#define K_DIM     1024       // 8 relations * 128

// Scratch (static device globals — no allocation allowed)
__device__ __half g_hf[N_NODES * FOLD_DIM];        // folded h  [N, 128] fp16
__device__ __half g_U [(size_t)M_PAD * K_DIM];     // aggregated [M_PAD, 1024] fp16
__device__ __half g_Bt[(size_t)OUT_DIM * K_DIM];   // basis^T, K-major, fp16

// ---------------------------------------------------------------------------
// Kernel 1: fold h with w_comp.  hf[n, q*4+b] = sum_p h[n, q*8+p] * w_comp[p,b]
// ---------------------------------------------------------------------------
__global__ void fold_kernel(const float* __restrict__ h,
                            const float* __restrict__ w_comp, int N) {
    __shared__ float wc[32];
    if (threadIdx.x < 32) wc[threadIdx.x] = w_comp[threadIdx.x];
    __syncthreads();

    int idx = blockIdx.x * blockDim.x + threadIdx.x;
    if (idx >= N * 32) return;
    int n = idx >> 5;
    int q = idx & 31;

    const float4* hp = reinterpret_cast<const float4*>(h + (size_t)n * IN_DIM + q * 8);
    float4 h0 = hp[0];
    float4 h1 = hp[1];
    float hv[8] = {h0.x, h0.y, h0.z, h0.w, h1.x, h1.y, h1.z, h1.w};

    float o[4];
    #pragma unroll
    for (int b = 0; b < 4; b++) {
        float s = 0.f;
        #pragma unroll
        for (int p = 0; p < 8; p++) s += hv[p] * wc[p * 4 + b];
        o[b] = s;
    }
    __half2 p0 = __floats2half2_rn(o[0], o[1]);
    __half2 p1 = __floats2half2_rn(o[2], o[3]);
    __half2* d = reinterpret_cast<__half2*>(g_hf + (size_t)n * FOLD_DIM + q * 4);
    d[0] = p0;
    d[1] = p1;
}

// ---------------------------------------------------------------------------
// Kernel 2: transpose basis [1024,256] -> g_Bt [256,1024] (K-major) as fp16.
// ---------------------------------------------------------------------------
__global__ void transpose_kernel(const float* __restrict__ basis) {
    __shared__ float t[32][33];
    int bx = blockIdx.x;
    int by = blockIdx.y;
    int x = threadIdx.x;
    int y = threadIdx.y;
    #pragma unroll
    for (int i = 0; i < 4; i++)
        t[y + i * 8][x] = basis[(size_t)(bx * 32 + y + i * 8) * OUT_DIM + by * 32 + x];
    __syncthreads();
    #pragma unroll
    for (int i = 0; i < 4; i++)
        g_Bt[(size_t)(by * 32 + y + i * 8) * K_DIM + bx * 32 + x] =
            __float2half_rn(t[x][y + i * 8]);
}

// ---------------------------------------------------------------------------
// Kernel 3: edge scatter, fp16. 16 lanes per edge, red.add.noftz.v4.f16x2
// ---------------------------------------------------------------------------
__global__ void scatter_kernel(const int* __restrict__ src,
                               const int* __restrict__ dst,
                               const int* __restrict__ etype, int E) {
    int warp = (blockIdx.x * blockDim.x + threadIdx.x) >> 5;
    int lane = threadIdx.x & 31;
    int e = warp * 2 + (lane >> 4);
    int l = lane & 15;
    if (e >= E) return;

    int s = __ldg(src + e);
    int d = __ldg(dst + e);
    int r = __ldg(etype + e);

    uint4 v = *reinterpret_cast<const uint4*>(g_hf + (size_t)s * FOLD_DIM + l * 8);
    __half* up = g_U + (size_t)d * K_DIM + r * FOLD_DIM + l * 8;
    asm volatile("red.global.add.noftz.v4.f16x2 [%0], {%1, %2, %3, %4};"
                 :: "l"(up), "r"(v.x), "r"(v.y), "r"(v.z), "r"(v.w)
                 : "memory");
}

// ---------------------------------------------------------------------------
// Kernel 4: fp16 tensor-core GEMM + bias + relu.
// out[M,256] = relu(U[M,1024] @ Bt^T + bias)
// CTA 64x64, 128 threads, 2x2 warp grid (warp tile 32x32).
// BK=64, 2-stage cp.async, SW128 smem. ALL addresses precomputed/literal:
// LDSM addrs loop-invariant (stage offset folds into the imm field), staging
// offsets literal via unroll-by-2 + one pointer bump per outer iteration.
// ---------------------------------------------------------------------------
#define GBM 64
#define GBN 64
#define GBK 64
#define STAGE_BYTES (GBM * 128)                       // 8192 B per operand-stage
#define GEMM_SMEM_BYTES (2 * 2 * STAGE_BYTES)         // 32768 B

#define SWZ(o) ((o) ^ (((o) >> 3) & 0x70))

__device__ __forceinline__ uint32_t smem_u32(const void* p) {
    return (uint32_t)__cvta_generic_to_shared(p);
}

__global__ __launch_bounds__(128, 5)
void gemm_tc_kernel(const __half* __restrict__ Bt,
                    const float* __restrict__ bias,
                    float* __restrict__ out, int M) {
    extern __shared__ char smem[];
    char* As = smem;                        // stages at +0, +8192
    char* Bs = smem + 2 * STAGE_BYTES;      // stages at +0, +8192

    int tid  = threadIdx.x;
    int lane = tid & 31;
    int warp = tid >> 5;
    int wm = warp & 1;                      // rows wm*32
    int wn = warp >> 1;                     // cols wn*32
    int bm = blockIdx.y * GBM;
    int bn = blockIdx.x * GBN;

    float acc[2][4][4];                     // [mf][nf][4]
    #pragma unroll
    for (int mf = 0; mf < 2; mf++)
        #pragma unroll
        for (int nf = 0; nf < 4; nf++)
            #pragma unroll
            for (int i = 0; i < 4; i++) acc[mf][nf][i] = 0.f;

    // ---- staging bases (all further offsets are compile-time literals) ----
    int r0  = tid >> 3;                    // 0..15; covers rows r0 + 16i
    int seg = tid & 7;
    uint32_t c_st = (uint32_t)(r0 & 7) << 4;   // swizzle const: invariant in i
    uint32_t daA = smem_u32(As) + r0 * 128 + ((uint32_t)(seg * 16) ^ c_st);
    uint32_t daB = smem_u32(Bs) + r0 * 128 + ((uint32_t)(seg * 16) ^ c_st);
    const __half* gA = g_U + (size_t)(bm + r0) * K_DIM + seg * 8;
    const __half* gB = Bt + (size_t)(bn + r0) * K_DIM + seg * 8;

    // STGOFF, KOFF are literals; row offset i*2048 smem / i*16*K_DIM gmem literal
    #define ISSUE_STAGE(STGOFF, KOFF)                                           \
        do {                                                                    \
            _Pragma("unroll")                                                   \
            for (int i = 0; i < 4; i++) {                                       \
                asm volatile("cp.async.cg.shared.global [%0], [%1], 16;"        \
                             :: "r"(daA + (STGOFF) + i * 2048),                 \
                                "l"(gA + (KOFF) + i * 16 * K_DIM) : "memory");  \
                asm volatile("cp.async.cg.shared.global [%0], [%1], 16;"        \
                             :: "r"(daB + (STGOFF) + i * 2048),                 \
                                "l"(gB + (KOFF) + i * 16 * K_DIM) : "memory");  \
            }                                                                   \
            asm volatile("cp.async.commit_group;" ::: "memory");                \
        } while (0)

    // ---- fragment LDSM addresses, stage 0 (loop-invariant) ----
    int frow = lane & 15;
    int fkb  = (lane >> 4) * 16;
    uint32_t aaddr[2][4], baddr[2][4];
    {
        uint32_t abase = smem_u32(As);
        uint32_t bbase = smem_u32(Bs);
        #pragma unroll
        for (int mf = 0; mf < 2; mf++) {
            int row = wm * 32 + mf * 16 + frow;
            uint32_t c = (uint32_t)(row & 7) << 4;
            #pragma unroll
            for (int ks = 0; ks < 4; ks++)
                aaddr[mf][ks] = abase + row * 128 + ((uint32_t)(ks * 32 + fkb) ^ c);
        }
        #pragma unroll
        for (int p = 0; p < 2; p++) {
            int row = wn * 32 + p * 16 + frow;
            uint32_t c = (uint32_t)(row & 7) << 4;
            #pragma unroll
            for (int ks = 0; ks < 4; ks++)
                baddr[p][ks] = bbase + row * 128 + ((uint32_t)(ks * 32 + fkb) ^ c);
        }
    }

    // COFF literal (0 or 8192): ptxas folds into the LDSM immediate
    #define COMPUTE(COFF)                                                           \
        do {                                                                        \
            _Pragma("unroll")                                                       \
            for (int ks = 0; ks < 4; ks++) {                                        \
                uint32_t afr[2][4];                                                 \
                _Pragma("unroll")                                                   \
                for (int mf = 0; mf < 2; mf++)                                      \
                    asm volatile(                                                   \
                        "ldmatrix.sync.aligned.m8n8.x4.shared.b16 {%0,%1,%2,%3}, [%4];" \
                        : "=r"(afr[mf][0]), "=r"(afr[mf][1]),                       \
                          "=r"(afr[mf][2]), "=r"(afr[mf][3])                        \
                        : "r"(aaddr[mf][ks] + (COFF)));                             \
                uint32_t bfr[4][2];                                                 \
                _Pragma("unroll")                                                   \
                for (int p = 0; p < 2; p++) {                                       \
                    uint32_t r0_, r1_, r2_, r3_;                                    \
                    asm volatile(                                                   \
                        "ldmatrix.sync.aligned.m8n8.x4.shared.b16 {%0,%1,%2,%3}, [%4];" \
                        : "=r"(r0_), "=r"(r1_), "=r"(r2_), "=r"(r3_)                \
                        : "r"(baddr[p][ks] + (COFF)));                              \
                    bfr[2 * p][0] = r0_; bfr[2 * p + 1][0] = r1_;                   \
                    bfr[2 * p][1] = r2_; bfr[2 * p + 1][1] = r3_;                   \
                }                                                                   \
                _Pragma("unroll")                                                   \
                for (int mf = 0; mf < 2; mf++)                                      \
                    _Pragma("unroll")                                               \
                    for (int nf = 0; nf < 4; nf++)                                  \
                        asm volatile(                                               \
                            "mma.sync.aligned.m16n8k16.row.col.f32.f16.f16.f32 "    \
                            "{%0,%1,%2,%3}, {%4,%5,%6,%7}, {%8,%9}, {%0,%1,%2,%3};" \
                            : "+f"(acc[mf][nf][0]), "+f"(acc[mf][nf][1]),           \
                              "+f"(acc[mf][nf][2]), "+f"(acc[mf][nf][3])            \
                            : "r"(afr[mf][0]), "r"(afr[mf][1]),                     \
                              "r"(afr[mf][2]), "r"(afr[mf][3]),                     \
                              "r"(bfr[nf][0]), "r"(bfr[nf][1]));                    \
            }                                                                       \
        } while (0)

    // prologue: stage 0 <- k=0
    ISSUE_STAGE(0, 0);

    // unroll-by-2: 16 k-chunks as 8 outer iterations with explicit stage parity
    for (int it2 = 0; it2 < 8; ++it2) {
        // half A: consume stage0 (k = it2*128), fill stage1 (k = it2*128 + 64)
        asm volatile("cp.async.wait_group 0;" ::: "memory");
        __syncthreads();
        ISSUE_STAGE(STAGE_BYTES, 64);      // always valid: k = 64..960
        COMPUTE(0);

        // half B: consume stage1, fill stage0 (k = it2*128 + 128)
        asm volatile("cp.async.wait_group 0;" ::: "memory");
        __syncthreads();
        if (it2 < 7) ISSUE_STAGE(0, 128);
        COMPUTE(STAGE_BYTES);

        gA += 128;
        gB += 128;
    }

    // epilogue: + bias, relu
    #pragma unroll
    for (int mf = 0; mf < 2; mf++) {
        int row0 = bm + wm * 32 + mf * 16 + (lane >> 2);
        #pragma unroll
        for (int nf = 0; nf < 4; nf++) {
            int col = bn + wn * 32 + nf * 8 + (lane & 3) * 2;
            float b0 = __ldg(bias + col);
            float b1 = __ldg(bias + col + 1);
            if (row0 < M) {
                float2 o;
                o.x = fmaxf(acc[mf][nf][0] + b0, 0.f);
                o.y = fmaxf(acc[mf][nf][1] + b1, 0.f);
                *reinterpret_cast<float2*>(out + (size_t)row0 * OUT_DIM + col) = o;
            }
            if (row0 + 8 < M) {
                float2 o;
                o.x = fmaxf(acc[mf][nf][2] + b0, 0.f);
                o.y = fmaxf(acc[mf][nf][3] + b1, 0.f);
                *reinterpret_cast<float2*>(out + (size_t)(row0 + 8) * OUT_DIM + col) = o;
            }
        }
    }
}

// ---------------------------------------------------------------------------
extern "C" void kernel_launch(void* const* d_in, const int* in_sizes, int n_in,
                              void* d_out, int out_size) {
    const float* h      = (const float*)d_in[0];
    const float* basis  = (const float*)d_in[1];
    const float* w_comp = (const float*)d_in[2];
    const float* bias   = (const float*)d_in[3];
    const int*   src    = (const int*)d_in[4];
    const int*   dst    = (const int*)d_in[5];
    const int*   etype  = (const int*)d_in[6];
    float* out = (float*)d_out;

    int N = in_sizes[0] / IN_DIM;   // 20000
    int E = in_sizes[4];            // 320000

    static cudaStream_t s1 = nullptr, s2 = nullptr;
    static cudaEvent_t e0 = nullptr, e1 = nullptr, e2 = nullptr;
    static bool init_done = false;
    if (!init_done) {
        cudaFuncSetAttribute(gemm_tc_kernel,
                             cudaFuncAttributeMaxDynamicSharedMemorySize,
                             GEMM_SMEM_BYTES);
        cudaStreamCreateWithFlags(&s1, cudaStreamNonBlocking);
        cudaStreamCreateWithFlags(&s2, cudaStreamNonBlocking);
        cudaEventCreateWithFlags(&e0, cudaEventDisableTiming);
        cudaEventCreateWithFlags(&e1, cudaEventDisableTiming);
        cudaEventCreateWithFlags(&e2, cudaEventDisableTiming);
        init_done = true;
    }

    void* uptr = nullptr;
    cudaGetSymbolAddress(&uptr, g_U);
    __half* btp = nullptr;
    cudaGetSymbolAddress((void**)&btp, g_Bt);

    // fork: memset U on s1; transpose on s2 (joined only before GEMM)
    cudaEventRecord(e0, 0);
    cudaStreamWaitEvent(s1, e0, 0);
    cudaStreamWaitEvent(s2, e0, 0);

    cudaMemsetAsync(uptr, 0, (size_t)M_PAD * K_DIM * sizeof(__half), s1);  // #1
    cudaEventRecord(e1, s1);

    fold_kernel<<<(N * 32 + 255) / 256, 256>>>(h, w_comp, N);              // #2

    transpose_kernel<<<dim3(32, 8), dim3(32, 8), 0, s2>>>(basis);          // #3
    cudaEventRecord(e2, s2);

    cudaStreamWaitEvent(0, e1, 0);   // scatter needs zeroed U (+ fold on main)

    scatter_kernel<<<(E + 15) / 16, 256>>>(src, dst, etype, E);            // #4

    cudaStreamWaitEvent(0, e2, 0);   // GEMM needs Bt

    dim3 grid(OUT_DIM / GBN, M_PAD / GBM);   // (4, 314)
    gemm_tc_kernel<<<grid, 128, GEMM_SMEM_BYTES>>>(btp, bias, out, N);     // #5 (ncu)
}